// round 9
// baseline (speedup 1.0000x reference)
#include <cuda_runtime.h>
#include <cuda_bf16.h>
#include <cub/cub.cuh>
#include <math.h>

#define NNODES 10000
#define BATCH  2000
#define NPAIRS (BATCH*(BATCH-1)/2)   /* 1999000 */
#define EMAX   5000000
#define SEL_THREADS 1024

#define PB      1024
#define CHUNK1  4884                 /* keygen/scatter chunk: PB*CHUNK1 >= EMAX, %4==0 */
#define CAP     2560000              /* per-segment capacity (expected 2.5M, +53 sigma) */
#define CHUNKA  (CAP/PB)             /* 2500, %4==0 */
#define PIV     37497500u            /* rowbase(5000): balanced mass split */
#define PIVK    (PIV*64u)            /* pivot in key space (flat<<6) */

// ---------------- static device scratch (no allocations allowed) -----------
__device__ unsigned int g_kin [EMAX];       // staged keys (linear)
__device__ unsigned int g_vin [EMAX];       // staged time bits
__device__ unsigned int g_ka0[CAP], g_ka1[CAP], g_va0[CAP], g_va1[CAP];
__device__ unsigned int g_kb0[CAP], g_kb1[CAP], g_vb0[CAP], g_vb1[CAP];
__device__ unsigned int g_h2[PB * 2];
__device__ unsigned int g_cnt[2];           // cntA, cntB
__device__ unsigned int g_h4[PB * 4];
__device__ unsigned int g_b4[4];
__device__ unsigned int g_scores[NNODES];
__device__ unsigned int g_nodes[BATCH];
__device__ int          g_flags[NNODES];
__device__ unsigned char g_temp[96u * 1024u * 1024u];   // 2 x 48MB cub temps

__device__ __forceinline__ unsigned int rotl32(unsigned int x, unsigned int d) {
    return (x << d) | (x >> (32u - d));
}

// ---------------- node chain: scores / select / pairs ----------------------
__global__ void k_scores() {
    int w = blockIdx.x * blockDim.x + threadIdx.x;
    if (w >= NNODES) return;
    const unsigned int k0 = 0u, k1 = 19u;
    const unsigned int ks[3] = { k0, k1, k0 ^ k1 ^ 0x1BD11BDAu };
    const unsigned int rotA[4] = {13u, 15u, 26u, 6u};
    const unsigned int rotB[4] = {17u, 29u, 16u, 24u};
    unsigned int x0 = 0u, x1 = (unsigned int)w;
    x0 += ks[0]; x1 += ks[1];
    #pragma unroll
    for (int i = 0; i < 5; i++) {
        #pragma unroll
        for (int r = 0; r < 4; r++) {
            unsigned int rot = (i & 1) ? rotB[r] : rotA[r];
            x0 += x1; x1 = rotl32(x1, rot); x1 ^= x0;
        }
        x0 += ks[(i + 1) % 3];
        x1 += ks[(i + 2) % 3] + (unsigned int)(i + 1);
    }
    unsigned int bits = x0 ^ x1;
    float f = __uint_as_float((bits >> 9) | 0x3F800000u) - 1.0f;
    float u = fmaxf(f, 1.17549435e-38f);
    float g = -logf(-logf(u));
    float s = (w > 0) ? (logf((float)w) + g) : -INFINITY;
    unsigned int b = __float_as_uint(s);
    unsigned int m = (b & 0x80000000u) ? ~b : (b | 0x80000000u);
    g_scores[w] = m;
}

__global__ void __launch_bounds__(SEL_THREADS) k_select(float* __restrict__ out) {
    __shared__ unsigned int s[NNODES];
    __shared__ unsigned int hist[256];
    __shared__ unsigned int sh_b, sh_rem, sh_run_eq, sh_run_sel;
    typedef cub::BlockScan<unsigned int, SEL_THREADS> Scan;
    __shared__ typename Scan::TempStorage scan_tmp;

    int tid = threadIdx.x;
    for (int e = tid; e < NNODES; e += SEL_THREADS) s[e] = g_scores[e];
    if (tid == 0) { sh_rem = BATCH; sh_run_eq = 0; sh_run_sel = 0; }
    __syncthreads();

    unsigned int prefix = 0;
    #pragma unroll
    for (int shift = 24; shift >= 0; shift -= 8) {
        if (tid < 256) hist[tid] = 0;
        __syncthreads();
        unsigned int mask_hi = (shift == 24) ? 0u : (0xFFFFFFFFu << (shift + 8));
        for (int e = tid; e < NNODES; e += SEL_THREADS) {
            unsigned int v = s[e];
            if (((v ^ prefix) & mask_hi) == 0u)
                atomicAdd(&hist[(v >> shift) & 255u], 1u);
        }
        __syncthreads();
        if (tid == 0) {
            unsigned int rem = sh_rem, acc = 0; int b = 0;
            for (int k = 255; k >= 0; k--) {
                unsigned int c = hist[k];
                if (acc + c >= rem) { b = k; break; }
                acc += c;
            }
            sh_b = (unsigned int)b; sh_rem = rem - acc;
        }
        __syncthreads();
        prefix |= sh_b << shift;
        __syncthreads();
    }
    unsigned int thr = prefix, rem = sh_rem;

    for (int base = 0; base < NNODES; base += SEL_THREADS) {
        int e = base + tid;
        unsigned int v = (e < NNODES) ? s[e] : 0u;
        unsigned int is_eq = (e < NNODES && v == thr) ? 1u : 0u;
        unsigned int is_gt = (e < NNODES && v >  thr) ? 1u : 0u;
        unsigned int eq_rank, eq_tot;
        Scan(scan_tmp).ExclusiveSum(is_eq, eq_rank, eq_tot);
        __syncthreads();
        unsigned int sel = is_gt | ((is_eq && (sh_run_eq + eq_rank) < rem) ? 1u : 0u);
        unsigned int pos, sel_tot;
        Scan(scan_tmp).ExclusiveSum(sel, pos, sel_tot);
        __syncthreads();
        unsigned int gpos = sh_run_sel + pos;
        if (e < NNODES) {
            g_flags[e] = (int)sel;
            if (sel) { g_nodes[gpos] = (unsigned int)e; out[gpos] = (float)e; }
        }
        __syncthreads();
        if (tid == 0) { sh_run_eq += eq_tot; sh_run_sel += sel_tot; }
        __syncthreads();
    }
}

__global__ void k_pairs(float* __restrict__ out) {
    int p = blockIdx.x * blockDim.x + threadIdx.x;
    if (p >= NPAIRS) return;
    const float A = 2.0f * BATCH - 1.0f;
    float disc = A * A - 8.0f * (float)p;
    int i = (int)((A - sqrtf(fmaxf(disc, 0.0f))) * 0.5f);
    if (i < 0) i = 0;
    if (i > BATCH - 2) i = BATCH - 2;
    while (i > 0 && (long long)i * (2 * BATCH - i - 1) / 2 > (long long)p) i--;
    while ((long long)(i + 1) * (2 * BATCH - i - 2) / 2 <= (long long)p) i++;
    long long bse = (long long)i * (2 * BATCH - i - 1) / 2;
    int j = i + 1 + (int)((long long)p - bse);
    out[BATCH + p]          = (float)__ldg(&g_nodes[i]);
    out[BATCH + NPAIRS + p] = (float)__ldg(&g_nodes[j]);
}

// ---------------- prefill: pad keys = 0xFFFFFFFF (sort to tail) -------------
__global__ void k_prefill() {
    int t4 = (blockIdx.x * blockDim.x + threadIdx.x) * 4;
    uint4 pad = make_uint4(~0u, ~0u, ~0u, ~0u);
    if (t4 < CAP) *(uint4*)(g_ka0 + t4) = pad;
    else if (t4 < 2 * CAP) *(uint4*)(g_kb0 + (t4 - CAP)) = pad;
}

// ---------------- keygen: stage keys/vals + per-block 2-bin hist ------------
// key = flat<<6 | state ; bin = (i >= 5000)
__global__ void __launch_bounds__(256) k_keygen(const int* __restrict__ edges,
                                                const float* __restrict__ times,
                                                const int* __restrict__ states, int E) {
    __shared__ unsigned int h[2];
    int b = blockIdx.x;
    int start = b * CHUNK1, end = min(E, start + CHUNK1);
    if (threadIdx.x < 2) h[threadIdx.x] = 0;
    __syncthreads();
    unsigned int c0 = 0, cn = 0;
    for (int base = start; base < end; base += 1024) {
        int t4 = base + threadIdx.x * 4;
        if (t4 + 3 < end) {
            int4 iv = *(const int4*)(edges + t4);
            int4 jv = *(const int4*)(edges + E + t4);
            int4 sv = *(const int4*)(states + t4);
            uint4 tv = *(const uint4*)((const unsigned int*)times + t4);
            uint4 kv;
            kv.x = ((unsigned int)(iv.x * NNODES - (iv.x * (iv.x + 1)) / 2 + (jv.x - iv.x - 1)) << 6) | ((unsigned int)sv.x & 1u);
            kv.y = ((unsigned int)(iv.y * NNODES - (iv.y * (iv.y + 1)) / 2 + (jv.y - iv.y - 1)) << 6) | ((unsigned int)sv.y & 1u);
            kv.z = ((unsigned int)(iv.z * NNODES - (iv.z * (iv.z + 1)) / 2 + (jv.z - iv.z - 1)) << 6) | ((unsigned int)sv.z & 1u);
            kv.w = ((unsigned int)(iv.w * NNODES - (iv.w * (iv.w + 1)) / 2 + (jv.w - iv.w - 1)) << 6) | ((unsigned int)sv.w & 1u);
            *(uint4*)(g_kin + t4) = kv;
            *(uint4*)(g_vin + t4) = tv;
            c0 += (iv.x < 5000) + (iv.y < 5000) + (iv.z < 5000) + (iv.w < 5000);
            cn += 4;
        } else {
            for (int t = t4; t < end && t < t4 + 4; t++) {
                int i = edges[t], j = edges[E + t];
                unsigned int flat = (unsigned int)(i * NNODES - (i * (i + 1)) / 2 + (j - i - 1));
                g_kin[t] = (flat << 6) | ((unsigned int)states[t] & 1u);
                g_vin[t] = __float_as_uint(times[t]);
                c0 += (i < 5000);
                cn += 1;
            }
        }
    }
    if (c0)      atomicAdd(&h[0], c0);
    if (cn - c0) atomicAdd(&h[1], cn - c0);
    __syncthreads();
    if (threadIdx.x < 2) g_h2[b * 2 + threadIdx.x] = h[threadIdx.x];
}

// ---------------- scan of 2-bin block hists ----------------------------------
__global__ void __launch_bounds__(PB) k_scan2() {
    typedef cub::BlockScan<unsigned int, PB> Scan;
    __shared__ typename Scan::TempStorage tmp;
    int t = threadIdx.x;
    unsigned int v0 = g_h2[t * 2], v1 = g_h2[t * 2 + 1];
    unsigned int p0, a0, p1, a1;
    Scan(tmp).ExclusiveSum(v0, p0, a0);
    __syncthreads();
    Scan(tmp).ExclusiveSum(v1, p1, a1);
    g_h2[t * 2] = p0; g_h2[t * 2 + 1] = p1;
    if (t == 0) { g_cnt[0] = a0; g_cnt[1] = a1; }
}

// ---------------- stable 2-bin scatter into segment arrays ------------------
__global__ void __launch_bounds__(256) k_scatter2(int E) {
    __shared__ unsigned int run[2];
    __shared__ unsigned int wcnt[8][2];
    __shared__ unsigned int ttot[2];
    int b = blockIdx.x;
    int start = b * CHUNK1, end = min(E, start + CHUNK1);
    if (threadIdx.x < 2) run[threadIdx.x] = g_h2[b * 2 + threadIdx.x];
    __syncthreads();

    int warp = threadIdx.x >> 5, lane = threadIdx.x & 31;
    for (int base = start; base < end; base += 256) {
        int t = base + threadIdx.x;
        unsigned int key = 0, val = 0;
        int c = -1;
        if (t < end) { key = g_kin[t]; val = g_vin[t]; c = (key >= PIVK) ? 1 : 0; }
        unsigned int rank = 0;
        #pragma unroll
        for (int cc = 0; cc < 2; cc++) {
            unsigned int m = __ballot_sync(0xFFFFFFFFu, c == cc);
            if (c == cc) rank = __popc(m & ((1u << lane) - 1u));
            if (lane == 0) wcnt[warp][cc] = __popc(m);
        }
        __syncthreads();
        if (threadIdx.x < 2) {
            unsigned int acc = 0;
            #pragma unroll
            for (int w = 0; w < 8; w++) {
                unsigned int v = wcnt[w][threadIdx.x];
                wcnt[w][threadIdx.x] = acc;
                acc += v;
            }
            ttot[threadIdx.x] = acc;
        }
        __syncthreads();
        if (t < end) {
            unsigned int pos = run[c] + wcnt[warp][c] + rank;
            if (c == 0) { g_ka0[pos] = key;        g_va0[pos] = val; }
            else        { g_kb0[pos] = key - PIVK; g_vb0[pos] = val; }
        }
        __syncthreads();
        if (threadIdx.x < 2) run[threadIdx.x] += ttot[threadIdx.x];
        __syncthreads();
    }
}

// ---------------- segment A: 4-bin hist on sorted keys ----------------------
__global__ void __launch_bounds__(256) k_histA(const unsigned int* __restrict__ keys) {
    __shared__ unsigned int h[4];
    unsigned int cntA = g_cnt[0];
    int b = blockIdx.x;
    int start = b * CHUNKA, end = min((int)cntA, start + CHUNKA);
    if (threadIdx.x < 4) h[threadIdx.x] = 0;
    __syncthreads();
    for (int t = start + threadIdx.x; t < end; t += blockDim.x)
        atomicAdd(&h[keys[t] >> 30], 1u);
    __syncthreads();
    if (threadIdx.x < 4) g_h4[b * 4 + threadIdx.x] = h[threadIdx.x];
}

__global__ void __launch_bounds__(PB) k_scanA() {
    typedef cub::BlockScan<unsigned int, PB> Scan;
    __shared__ typename Scan::TempStorage tmp;
    __shared__ unsigned int tot[4];
    int t = threadIdx.x;
    unsigned int v[4];
    #pragma unroll
    for (int c = 0; c < 4; c++) v[c] = g_h4[t * 4 + c];
    #pragma unroll
    for (int c = 0; c < 4; c++) {
        unsigned int pre, agg;
        Scan(tmp).ExclusiveSum(v[c], pre, agg);
        g_h4[t * 4 + c] = pre;
        if (t == 0) tot[c] = agg;
        __syncthreads();
    }
    if (t == 0) {
        unsigned int off = 0;
        #pragma unroll
        for (int c = 0; c < 4; c++) { g_b4[c] = off; off += tot[c]; }
    }
}

// ---------------- flat -> (i,j) decode ---------------------------------------
__device__ __forceinline__ long long rowbase(int i) {
    return (long long)i * (2 * NNODES - 1 - i) / 2;
}
__device__ __forceinline__ void decode_flat(unsigned int flat, int& i, int& j) {
    const float A = 2.0f * NNODES - 1.0f;
    float disc = A * A - 8.0f * (float)flat;
    i = (int)((A - sqrtf(fmaxf(disc, 0.0f))) * 0.5f);
    if (i < 0) i = 0;
    if (i > NNODES - 2) i = NNODES - 2;
    while (i > 0 && rowbase(i) > (long long)flat) i--;
    while (rowbase(i + 1) <= (long long)flat) i++;
    j = (int)((long long)flat - rowbase(i)) + i + 1;
}

// ---------------- finish A: stable 4-bin partition fused with epilogue ------
__global__ void __launch_bounds__(256) k_finishA(const unsigned int* __restrict__ keys,
                                                 const unsigned int* __restrict__ vals,
                                                 float* __restrict__ out, int E) {
    __shared__ unsigned int run[4];
    __shared__ unsigned int wcnt[8][4];
    __shared__ unsigned int ttot[4];
    unsigned int cntA = g_cnt[0];
    int b = blockIdx.x;
    int start = b * CHUNKA, end = min((int)cntA, start + CHUNKA);
    if (threadIdx.x < 4)
        run[threadIdx.x] = g_h4[b * 4 + threadIdx.x] + g_b4[threadIdx.x];
    __syncthreads();

    const long long OFF_E = (long long)BATCH + 2LL * NPAIRS;
    const long long OFF_T = OFF_E + 2LL * E;
    const long long OFF_S = OFF_T + E;
    const long long OFF_M = OFF_S + E;

    int warp = threadIdx.x >> 5, lane = threadIdx.x & 31;
    for (int base = start; base < end; base += 256) {
        int t = base + threadIdx.x;
        unsigned int key = 0, val = 0;
        int c = -1;
        if (t < end) { key = keys[t]; val = vals[t]; c = (int)(key >> 30); }
        unsigned int rank = 0;
        #pragma unroll
        for (int cc = 0; cc < 4; cc++) {
            unsigned int m = __ballot_sync(0xFFFFFFFFu, c == cc);
            if (c == cc) rank = __popc(m & ((1u << lane) - 1u));
            if (lane == 0) wcnt[warp][cc] = __popc(m);
        }
        __syncthreads();
        if (threadIdx.x < 4) {
            unsigned int acc = 0;
            #pragma unroll
            for (int w = 0; w < 8; w++) {
                unsigned int v = wcnt[w][threadIdx.x];
                wcnt[w][threadIdx.x] = acc;
                acc += v;
            }
            ttot[threadIdx.x] = acc;
        }
        __syncthreads();
        if (t < end) {
            unsigned int pos = run[c] + wcnt[warp][c] + rank;  // global out slot in [0,cntA)
            unsigned int flat = key >> 6;
            int st = (int)(key & 1u);
            int i, j; decode_flat(flat, i, j);
            int m = g_flags[i] & g_flags[j];
            out[OFF_E + pos]     = (float)i;
            out[OFF_E + E + pos] = (float)j;
            out[OFF_T + pos]     = m ? __uint_as_float(val) : 0.0f;
            out[OFF_S + pos]     = m ? (float)st : 0.0f;
            out[OFF_M + pos]     = (float)m;
        }
        __syncthreads();
        if (threadIdx.x < 4) run[threadIdx.x] += ttot[threadIdx.x];
        __syncthreads();
    }
}

// ---------------- finish B: sorted order is final; pure epilogue ------------
__global__ void __launch_bounds__(256) k_finishB(const unsigned int* __restrict__ keys,
                                                 const unsigned int* __restrict__ vals,
                                                 float* __restrict__ out, int E) {
    unsigned int cntA = g_cnt[0], cntB = g_cnt[1];
    unsigned int t = blockIdx.x * blockDim.x + threadIdx.x;
    if (t >= cntB) return;
    unsigned int key = keys[t];
    unsigned int flat = (key >> 6) + PIV;
    int st = (int)(key & 1u);
    int i, j; decode_flat(flat, i, j);
    int m = g_flags[i] & g_flags[j];
    unsigned int pos = cntA + t;

    const long long OFF_E = (long long)BATCH + 2LL * NPAIRS;
    const long long OFF_T = OFF_E + 2LL * E;
    const long long OFF_S = OFF_T + E;
    const long long OFF_M = OFF_S + E;

    out[OFF_E + pos]     = (float)i;
    out[OFF_E + E + pos] = (float)j;
    out[OFF_T + pos]     = m ? __uint_as_float(vals[t]) : 0.0f;
    out[OFF_S + pos]     = m ? (float)st : 0.0f;
    out[OFF_M + pos]     = (float)m;
}

// ---------------- launcher ---------------------------------------------------
extern "C" void kernel_launch(void* const* d_in, const int* in_sizes, int n_in,
                              void* d_out, int out_size) {
    const int*   edges  = (const int*)d_in[0];
    const float* times  = (const float*)d_in[1];
    const int*   states = (const int*)d_in[2];
    int E = in_sizes[1];
    if (E > EMAX) E = EMAX;
    float* out = (float*)d_out;

    static cudaStream_t s_side = nullptr;
    static cudaEvent_t ev1 = nullptr, ev2 = nullptr;
    if (s_side == nullptr) {
        cudaStreamCreateWithFlags(&s_side, cudaStreamNonBlocking);
        cudaEventCreateWithFlags(&ev1, cudaEventDisableTiming);
        cudaEventCreateWithFlags(&ev2, cudaEventDisableTiming);
    }

    void *ka0, *ka1, *va0, *va1, *kb0, *kb1, *vb0, *vb1, *temp;
    cudaGetSymbolAddress(&ka0, g_ka0); cudaGetSymbolAddress(&ka1, g_ka1);
    cudaGetSymbolAddress(&va0, g_va0); cudaGetSymbolAddress(&va1, g_va1);
    cudaGetSymbolAddress(&kb0, g_kb0); cudaGetSymbolAddress(&kb1, g_kb1);
    cudaGetSymbolAddress(&vb0, g_vb0); cudaGetSymbolAddress(&vb1, g_vb1);
    cudaGetSymbolAddress(&temp, g_temp);
    const size_t temp_half = 48u * 1024u * 1024u;

    // ---- FORK (required for graph capture): ev1 record #1 on main ----------
    cudaEventRecord(ev1, 0);
    cudaStreamWaitEvent(s_side, ev1, 0);

    // ---- side stream: node chain --------------------------------------------
    k_scores<<<(NNODES + 255) / 256, 256, 0, s_side>>>();
    k_select<<<1, SEL_THREADS, 0, s_side>>>(out);
    k_pairs<<<(NPAIRS + 255) / 256, 256, 0, s_side>>>(out);

    // ---- main: prefill pads, keygen + hist, scan, stable 2-bin scatter -----
    k_prefill<<<(2 * CAP / 4 + 255) / 256, 256>>>();
    k_keygen<<<PB, 256>>>(edges, times, states, E);
    k_scan2<<<1, PB>>>();
    k_scatter2<<<PB, 256>>>(E);

    // ---- ev1 record #2: scatter done -> side stream may start B sort --------
    cudaEventRecord(ev1, 0);
    cudaStreamWaitEvent(s_side, ev1, 0);

    // ---- segment A sort on main; segment B sort on side ---------------------
    cub::DoubleBuffer<unsigned int> dkA((unsigned int*)ka0, (unsigned int*)ka1);
    cub::DoubleBuffer<unsigned int> dvA((unsigned int*)va0, (unsigned int*)va1);
    cub::DoubleBuffer<unsigned int> dkB((unsigned int*)kb0, (unsigned int*)kb1);
    cub::DoubleBuffer<unsigned int> dvB((unsigned int*)vb0, (unsigned int*)vb1);

    size_t tbA = 0;
    cub::DeviceRadixSort::SortPairs(nullptr, tbA, dkA, dvA, CAP, 6, 30);
    if (tbA > temp_half) tbA = temp_half;
    cub::DeviceRadixSort::SortPairs(temp, tbA, dkA, dvA, CAP, 6, 30);

    size_t tbB = 0;
    cub::DeviceRadixSort::SortPairs(nullptr, tbB, dkB, dvB, CAP, 6, 30);
    if (tbB > temp_half) tbB = temp_half;
    cub::DeviceRadixSort::SortPairs((unsigned char*)temp + temp_half, tbB,
                                    dkB, dvB, CAP, 6, 30, s_side);
    cudaEventRecord(ev2, s_side);

    // ---- A finish partition prep on main ------------------------------------
    k_histA<<<PB, 256>>>(dkA.Current());
    k_scanA<<<1, PB>>>();

    // ---- join, then both epilogues ------------------------------------------
    cudaStreamWaitEvent(0, ev2, 0);
    k_finishA<<<PB, 256>>>(dkA.Current(), dvA.Current(), out, E);
    k_finishB<<<(CAP + 255) / 256, 256>>>(dkB.Current(), dvB.Current(), out, E);
}